// round 14
// baseline (speedup 1.0000x reference)
#include <cuda_runtime.h>
#include <cuda_bf16.h>
#include <math.h>

typedef unsigned int u32;

#define BATCH 64
#define CH 512
#define WD 512
#define NPIX 16
#define NCOL (CH*NPIX)   /* 8192 */
#define TN 64            /* n-tile = 4 out-ch x 16 px */
#define KCH 64           /* k per chunk */
#define NCHUNK 8
#define KPAD 72          /* padded row elems (144B) */
#define ROWB 144
#define MATB (64*ROWB)   /* 9216 B per matrix */
#define STAGEB (4*MATB)  /* 36864 B per stage */
#define SMEM_MMA (3*STAGEB)

// ---- scratch (allocation-free rule: __device__ globals) ----
__device__ __align__(16) float g_s2[BATCH*CH];
__device__ __align__(16) __nv_bfloat16 g_Sh[BATCH*CH];
__device__ __align__(16) __nv_bfloat16 g_Sl[BATCH*CH];
__device__ __align__(16) __nv_bfloat16 g_Uh[CH*NCOL];   // 8MB  U hi [k][n]
__device__ __align__(16) __nv_bfloat16 g_Ul[CH*NCOL];   // 8MB  U lo [k][n]
__device__ __align__(16) float g_q[CH*CH];              // q[k][o]
__device__ __align__(16) float g_d[BATCH*CH];           // demod [b][o]

// ---- helpers (sm_80-era ISA; valid in compute_100 PTX) ----
__device__ __forceinline__ u32 smem_u32(const void* p) {
    u32 a;
    asm("{ .reg .u64 t; cvta.to.shared.u64 t, %1; cvt.u32.u64 %0, t; }" : "=r"(a) : "l"(p));
    return a;
}
__device__ __forceinline__ void ldsm_x4(u32* r, u32 addr) {
    asm volatile("ldmatrix.sync.aligned.m8n8.x4.shared.b16 {%0,%1,%2,%3}, [%4];"
        : "=r"(r[0]), "=r"(r[1]), "=r"(r[2]), "=r"(r[3]) : "r"(addr));
}
__device__ __forceinline__ void ldsm_x2_trans(u32* r, u32 addr) {
    asm volatile("ldmatrix.sync.aligned.m8n8.x2.trans.shared.b16 {%0,%1}, [%2];"
        : "=r"(r[0]), "=r"(r[1]) : "r"(addr));
}
__device__ __forceinline__ void mma16816(float* c, const u32* a, const u32* b) {
    asm volatile("mma.sync.aligned.m16n8k16.row.col.f32.bf16.bf16.f32 "
        "{%0,%1,%2,%3}, {%4,%5,%6,%7}, {%8,%9}, {%0,%1,%2,%3};"
        : "+f"(c[0]), "+f"(c[1]), "+f"(c[2]), "+f"(c[3])
        : "r"(a[0]), "r"(a[1]), "r"(a[2]), "r"(a[3]), "r"(b[0]), "r"(b[1]));
}
__device__ __forceinline__ void cpasync16(u32 dst, const __nv_bfloat16* src) {
    asm volatile("cp.async.cg.shared.global [%0], [%1], 16;"
        :: "r"(dst), "l"(__cvta_generic_to_global((void*)src)));
}
#define CP_COMMIT() asm volatile("cp.async.commit_group;" ::: "memory")
#define CP_WAIT1()  asm volatile("cp.async.wait_group 1;" ::: "memory")
#define CP_WAIT0()  asm volatile("cp.async.wait_group 0;" ::: "memory")

// ============== Kernel A: style dense, barrier-free ==============
// grid 128 (4 c each), 256 threads = 64 b x 4 c.
__global__ __launch_bounds__(256) void style_kernel(
        const float* __restrict__ w0,
        const float* __restrict__ mod_w,
        const float* __restrict__ mod_b) {
    const int tid = threadIdx.x;
    const int b = tid >> 2;
    const int c = blockIdx.x * 4 + (tid & 3);
    const float* wr = w0 + (size_t)b * WD;
    const float* mp = mod_w + c;

    float a0 = 0.f, a1 = 0.f;
    #pragma unroll 8
    for (int k = 0; k < WD; k += 2) {
        a0 = fmaf(wr[k],     mp[(size_t)k * CH],       a0);
        a1 = fmaf(wr[k + 1], mp[(size_t)(k + 1) * CH], a1);
    }
    const float inv = 1.0f / sqrtf((float)WD);
    float s = (a0 + a1) * inv + mod_b[c] + 1.0f;
    g_s2[(size_t)b * CH + c] = s * s;
    __nv_bfloat16 h = __float2bfloat16(s);
    g_Sh[(size_t)b * CH + c] = h;
    g_Sl[(size_t)b * CH + c] = __float2bfloat16(s - __bfloat162float(h));
}

// ============== Kernel B: U precompute (coalesced) ==============
// grid 1024 = 128 i-tiles(4) x 8 o-tiles(64); 256 threads = 4i x 64o.
__global__ __launch_bounds__(256) void uprep_kernel(
        const float* __restrict__ conv_w,
        const float* __restrict__ cst) {
    const int tid = threadIdx.x;
    const int it = blockIdx.x >> 3;
    const int ot = blockIdx.x & 7;
    const int i = it * 4 + (tid >> 6);
    const int o = ot * 64 + (tid & 63);

    __shared__ float cs[4][16];
    if (tid < 64) cs[tid >> 4][tid & 15] = cst[(it * 4 + (tid >> 4)) * NPIX + (tid & 15)];
    __syncthreads();

    const float coef = 1.0f / sqrtf(9.0f * (float)CH);
    float w9[9], q = 0.f;
    #pragma unroll
    for (int t = 0; t < 9; t++) {
        float w = conv_w[(size_t)t * CH * CH + (size_t)i * CH + o] * coef;
        w9[t] = w; q += w * w;
    }
    g_q[(size_t)i * CH + o] = q;

    float c16[NPIX];
    #pragma unroll
    for (int p = 0; p < NPIX; p++) c16[p] = cs[tid >> 6][p];

    u32 ph[8], pl[8];
    #pragma unroll
    for (int h = 0; h < 4; h++) {
        #pragma unroll
        for (int x2 = 0; x2 < 2; x2++) {
            float v[2];
            #pragma unroll
            for (int e = 0; e < 2; e++) {
                int x = x2 * 2 + e;
                float a = 0.f;
                #pragma unroll
                for (int kh = 0; kh < 3; kh++) {
                    int hh = h + kh - 1;
                    if (hh < 0 || hh >= 4) continue;
                    #pragma unroll
                    for (int kw = 0; kw < 3; kw++) {
                        int xx = x + kw - 1;
                        if (xx < 0 || xx >= 4) continue;
                        a += w9[kh * 3 + kw] * c16[hh * 4 + xx];
                    }
                }
                v[e] = a;
            }
            __nv_bfloat16 h0 = __float2bfloat16(v[0]);
            __nv_bfloat16 h1 = __float2bfloat16(v[1]);
            __nv_bfloat162 hp(h0, h1);
            __nv_bfloat162 lp(__float2bfloat16(v[0] - __bfloat162float(h0)),
                              __float2bfloat16(v[1] - __bfloat162float(h1)));
            ph[h * 2 + x2] = *(u32*)&hp;
            pl[h * 2 + x2] = *(u32*)&lp;
        }
    }
    uint4* dh = (uint4*)(g_Uh + (size_t)i * NCOL + o * 16);
    uint4* dl = (uint4*)(g_Ul + (size_t)i * NCOL + o * 16);
    dh[0] = make_uint4(ph[0], ph[1], ph[2], ph[3]);
    dh[1] = make_uint4(ph[4], ph[5], ph[6], ph[7]);
    dl[0] = make_uint4(pl[0], pl[1], pl[2], pl[3]);
    dl[1] = make_uint4(pl[4], pl[5], pl[6], pl[7]);
}

// ============== Kernel C: demod ==============
// grid 64 (8 o each), 512 threads.
__global__ __launch_bounds__(512) void demod_kernel() {
    __shared__ float q_s[CH][9];
    const int tid = threadIdx.x;
    const int o0 = blockIdx.x * 8;

    {
        float4 a = *(const float4*)&g_q[(size_t)tid * CH + o0];
        float4 b = *(const float4*)&g_q[(size_t)tid * CH + o0 + 4];
        q_s[tid][0] = a.x; q_s[tid][1] = a.y; q_s[tid][2] = a.z; q_s[tid][3] = a.w;
        q_s[tid][4] = b.x; q_s[tid][5] = b.y; q_s[tid][6] = b.z; q_s[tid][7] = b.w;
    }
    __syncthreads();

    const int b = tid >> 3;
    const int og = tid & 7;
    float acc = 1e-8f;
    const float4* sp = (const float4*)&g_s2[(size_t)b * CH];
    #pragma unroll 4
    for (int i4 = 0; i4 < CH / 4; i4++) {
        float4 s2v = sp[i4];
        acc = fmaf(s2v.x, q_s[i4 * 4 + 0][og], acc);
        acc = fmaf(s2v.y, q_s[i4 * 4 + 1][og], acc);
        acc = fmaf(s2v.z, q_s[i4 * 4 + 2][og], acc);
        acc = fmaf(s2v.w, q_s[i4 * 4 + 3][og], acc);
    }
    g_d[(size_t)b * CH + o0 + og] = rsqrtf(acc);
}

// ============== Kernel D: pipelined mma.sync GEMM + epilogue ==============
// grid 128 n-tiles of 64; 256 threads = 8 warps (2 wm x 4 wn).
// cp.async 3-stage ring: Ah | Al | Bh | Bl, 64 rows x 128B each.
__global__ __launch_bounds__(256) void mma_kernel(
        const float* __restrict__ noise,
        const float* __restrict__ ns_ptr,
        const float* __restrict__ bias,
        float* __restrict__ out) {
    extern __shared__ __align__(16) char smem[];
    const u32 sm0 = smem_u32(smem);

    const int tid = threadIdx.x;
    const int wid = tid >> 5;
    const int lane = tid & 31;
    const int wm = wid >> 2;
    const int wn = wid & 3;
    const int n0 = blockIdx.x * TN;
    const int o0 = n0 >> 4;

    // cp.async role: one row per thread (4 matrices x 64 rows)
    const int mrow = tid & 63;
    const int mat = tid >> 6;
    const __nv_bfloat16* src0;
    size_t step;
    if (mat == 0)      { src0 = g_Sh + (size_t)mrow * CH;          step = KCH; }
    else if (mat == 1) { src0 = g_Sl + (size_t)mrow * CH;          step = KCH; }
    else if (mat == 2) { src0 = g_Uh + (size_t)mrow * NCOL + n0;   step = (size_t)KCH * NCOL; }
    else               { src0 = g_Ul + (size_t)mrow * NCOL + n0;   step = (size_t)KCH * NCOL; }
    const u32 dst_off = (u32)(mat * MATB + mrow * ROWB);

    // prologue: stages 0,1
    #pragma unroll
    for (int p = 0; p < 2; p++) {
        u32 d = sm0 + p * STAGEB + dst_off;
        const __nv_bfloat16* s = src0 + (size_t)p * step;
        #pragma unroll
        for (int j = 0; j < 8; j++) cpasync16(d + j * 16, s + j * 8);
        CP_COMMIT();
    }

    const u32 aOff = (u32)(wm * 32 + (lane & 15)) * ROWB + (u32)(((lane >> 4) & 1) * 16);
    const u32 bRow = (u32)(lane & 15) * ROWB;

    float acc[2][2][4];
    #pragma unroll
    for (int mf = 0; mf < 2; mf++)
        #pragma unroll
        for (int nf = 0; nf < 2; nf++)
            #pragma unroll
            for (int e = 0; e < 4; e++) acc[mf][nf][e] = 0.f;

    for (int ck = 0; ck < NCHUNK; ck++) {
        if (ck < NCHUNK - 1) CP_WAIT1(); else CP_WAIT0();
        __syncthreads();

        // issue stage ck+2 (buffer (ck+2)%3 — its last reader was mma(ck-1), done by barrier)
        if (ck + 2 < NCHUNK) {
            int st = (ck + 2) % 3;
            u32 d = sm0 + st * STAGEB + dst_off;
            const __nv_bfloat16* s = src0 + (size_t)(ck + 2) * step;
            #pragma unroll
            for (int j = 0; j < 8; j++) cpasync16(d + j * 16, s + j * 8);
            CP_COMMIT();
        }

        const int st = ck % 3;
        const u32 ah_b = sm0 + st * STAGEB;
        const u32 al_b = ah_b + MATB;
        const u32 bh_b = ah_b + 2 * MATB;
        const u32 bl_b = ah_b + 3 * MATB;

        #pragma unroll
        for (int ks = 0; ks < 4; ks++) {
            u32 ah[2][4], al[2][4];
            ldsm_x4(ah[0], ah_b + aOff + (u32)(ks * 32));
            ldsm_x4(ah[1], ah_b + aOff + 16 * ROWB + (u32)(ks * 32));
            ldsm_x4(al[0], al_b + aOff + (u32)(ks * 32));
            ldsm_x4(al[1], al_b + aOff + 16 * ROWB + (u32)(ks * 32));
            const u32 krow = (u32)(ks * 16) * ROWB + bRow;
            #pragma unroll
            for (int nf = 0; nf < 2; nf++) {
                u32 bh[2], bl[2];
                const u32 ncol = (u32)(wn * 16 + nf * 8) * 2;
                ldsm_x2_trans(bh, bh_b + krow + ncol);
                ldsm_x2_trans(bl, bl_b + krow + ncol);
                #pragma unroll
                for (int mf = 0; mf < 2; mf++) {
                    mma16816(acc[mf][nf], ah[mf], bh);
                    mma16816(acc[mf][nf], ah[mf], bl);
                    mma16816(acc[mf][nf], al[mf], bh);
                }
            }
        }
    }
    __syncthreads();

    // ---- stage epilogue data (reuse smem as float buffer) ----
    float* ep = (float*)smem;   // [0..255] d[og][b], [256..1279] noise, [1280..1283] bias, [1284] nstr
    ep[tid] = g_d[(size_t)(tid & 63) * CH + o0 + (tid >> 6)];
    ((float4*)(ep + 256))[tid] = ((const float4*)noise)[tid];
    if (tid < 4) ep[1280 + tid] = bias[o0 + tid];
    if (tid == 4) ep[1284] = ns_ptr[0];
    __syncthreads();

    const float gain = 1.41421356237309515f;
    const float nstr = ep[1284];
    #pragma unroll
    for (int mf = 0; mf < 2; mf++) {
        #pragma unroll
        for (int nf = 0; nf < 2; nf++) {
            int row0 = wm * 32 + mf * 16 + (lane >> 2);
            int colb = wn * 16 + nf * 8 + 2 * (lane & 3);
            int ol2 = colb >> 4;
            int px = colb & 15;
            float bb = ep[1280 + ol2];
            #pragma unroll
            for (int hh = 0; hh < 2; hh++) {
                int b = row0 + hh * 8;
                float dv = ep[ol2 * 64 + b];
                float2 nz = *(const float2*)&ep[256 + b * NPIX + px];
                float x0 = acc[mf][nf][hh * 2 + 0] * dv + nz.x * nstr + bb;
                float x1 = acc[mf][nf][hh * 2 + 1] * dv + nz.y * nstr + bb;
                x0 = (x0 > 0.f ? x0 : 0.2f * x0) * gain;
                x1 = (x1 > 0.f ? x1 : 0.2f * x1) * gain;
                *(float2*)&out[(size_t)b * NCOL + n0 + colb] = make_float2(x0, x1);
            }
        }
    }
}

extern "C" void kernel_launch(void* const* d_in, const int* in_sizes, int n_in,
                              void* d_out, int out_size) {
    const float* w0     = (const float*)d_in[0];
    const float* cst    = (const float*)d_in[1];
    const float* conv_w = (const float*)d_in[2];
    const float* mod_w  = (const float*)d_in[3];
    const float* mod_b  = (const float*)d_in[4];
    const float* noise  = (const float*)d_in[5];
    const float* nstr   = (const float*)d_in[6];
    const float* bias   = (const float*)d_in[7];
    float* out = (float*)d_out;

    cudaFuncSetAttribute(mma_kernel,
        cudaFuncAttributeMaxDynamicSharedMemorySize, SMEM_MMA);

    uprep_kernel<<<1024, 256>>>(conv_w, cst);
    style_kernel<<<CH / 4, 256>>>(w0, mod_w, mod_b);
    demod_kernel<<<64, 512>>>();
    mma_kernel<<<NCOL / TN, 256, SMEM_MMA>>>(noise, nstr, bias, out);
}

// round 15
// speedup vs baseline: 1.4280x; 1.4280x over previous
#include <cuda_runtime.h>
#include <cuda_bf16.h>
#include <math.h>

typedef unsigned int u32;

#define BATCH 64
#define CH 512
#define WD 512
#define NPIX 16
#define NCOL (CH*NPIX)   /* 8192 */
#define TN 64
#define KCH 64
#define NCHUNK 8
#define ROWB 144
#define MATB (64*ROWB)   /* 9216 B */
#define STAGEB (4*MATB)  /* 36864 B */
#define NSTAGE 4
#define SMEM_MMA (NSTAGE*STAGEB)

// ---- scratch ----
__device__ __align__(16) float g_sp[8][BATCH*CH];       // style split-K partials
__device__ __align__(16) float g_s2[BATCH*CH];
__device__ __align__(16) __nv_bfloat16 g_Sh[BATCH*CH];
__device__ __align__(16) __nv_bfloat16 g_Sl[BATCH*CH];
__device__ __align__(16) __nv_bfloat16 g_Uh[CH*NCOL];   // 8MB
__device__ __align__(16) __nv_bfloat16 g_Ul[CH*NCOL];   // 8MB
__device__ __align__(16) float g_q[CH*CH];
__device__ __align__(16) float g_d[BATCH*CH];

// ---- helpers ----
__device__ __forceinline__ u32 smem_u32(const void* p) {
    u32 a;
    asm("{ .reg .u64 t; cvta.to.shared.u64 t, %1; cvt.u32.u64 %0, t; }" : "=r"(a) : "l"(p));
    return a;
}
__device__ __forceinline__ void ldsm_x4(u32* r, u32 addr) {
    asm volatile("ldmatrix.sync.aligned.m8n8.x4.shared.b16 {%0,%1,%2,%3}, [%4];"
        : "=r"(r[0]), "=r"(r[1]), "=r"(r[2]), "=r"(r[3]) : "r"(addr));
}
__device__ __forceinline__ void ldsm_x2_trans(u32* r, u32 addr) {
    asm volatile("ldmatrix.sync.aligned.m8n8.x2.trans.shared.b16 {%0,%1}, [%2];"
        : "=r"(r[0]), "=r"(r[1]) : "r"(addr));
}
__device__ __forceinline__ void mma16816(float* c, const u32* a, const u32* b) {
    asm volatile("mma.sync.aligned.m16n8k16.row.col.f32.bf16.bf16.f32 "
        "{%0,%1,%2,%3}, {%4,%5,%6,%7}, {%8,%9}, {%0,%1,%2,%3};"
        : "+f"(c[0]), "+f"(c[1]), "+f"(c[2]), "+f"(c[3])
        : "r"(a[0]), "r"(a[1]), "r"(a[2]), "r"(a[3]), "r"(b[0]), "r"(b[1]));
}
__device__ __forceinline__ void cpasync16(u32 dst, const __nv_bfloat16* src) {
    asm volatile("cp.async.cg.shared.global [%0], [%1], 16;"
        :: "r"(dst), "l"(__cvta_generic_to_global((void*)src)));
}
#define CP_COMMIT() asm volatile("cp.async.commit_group;" ::: "memory")
#define CP_WAIT(n)  asm volatile("cp.async.wait_group %0;" :: "n"(n) : "memory")

// ============== Kernel A1: style split-K partial ==============
// grid 64 = 8 c-tiles x 8 k-tiles; 256 threads.
__global__ __launch_bounds__(256) void style_partial(
        const float* __restrict__ w0,
        const float* __restrict__ mod_w) {
    __shared__ float w0t[64][68];    // [b][k]
    __shared__ float mwt[64][68];    // [k][c]
    const int tid = threadIdx.x;
    const int ct = blockIdx.x >> 3;
    const int kt = blockIdx.x & 7;
    const int c0 = ct * 64;
    const int k0 = kt * 64;

    #pragma unroll
    for (int q = 0; q < 4; q++) {
        int idx = tid + q*256;
        int r = idx >> 4, c4 = idx & 15;
        *(float4*)&w0t[r][c4*4] = *(const float4*)&w0[r*WD + k0 + c4*4];
        *(float4*)&mwt[r][c4*4] = *(const float4*)&mod_w[(size_t)(k0 + r)*CH + c0 + c4*4];
    }
    __syncthreads();

    const int c  = tid & 63;
    const int bg = tid >> 6;         // 4 groups of 16 b
    float acc[16];
    #pragma unroll
    for (int i = 0; i < 16; i++) acc[i] = 0.f;

    #pragma unroll 8
    for (int k = 0; k < 64; k++) {
        float mw = mwt[k][c];
        #pragma unroll
        for (int i = 0; i < 16; i++)
            acc[i] = fmaf(w0t[bg*16 + i][k], mw, acc[i]);
    }
    #pragma unroll
    for (int i = 0; i < 16; i++)
        g_sp[kt][(size_t)(bg*16 + i)*CH + c0 + c] = acc[i];
}

// ============== Kernel A2: style finish (merge partials, split bf16) ==============
// grid 64 (one b each), 512 threads (one c each).
__global__ __launch_bounds__(512) void style_finish(const float* __restrict__ mod_b) {
    const int b = blockIdx.x;
    const int c = threadIdx.x;
    const size_t idx = (size_t)b*CH + c;
    float a = 0.f;
    #pragma unroll
    for (int p = 0; p < 8; p++) a += g_sp[p][idx];
    const float inv = 1.0f / sqrtf((float)WD);
    float s = a*inv + mod_b[c] + 1.0f;
    g_s2[idx] = s*s;
    __nv_bfloat16 h = __float2bfloat16(s);
    g_Sh[idx] = h;
    g_Sl[idx] = __float2bfloat16(s - __bfloat162float(h));
}

// ============== Kernel B: U precompute (coalesced) ==============
__global__ __launch_bounds__(256) void uprep_kernel(
        const float* __restrict__ conv_w,
        const float* __restrict__ cst) {
    const int tid = threadIdx.x;
    const int it = blockIdx.x >> 3;
    const int ot = blockIdx.x & 7;
    const int i = it * 4 + (tid >> 6);
    const int o = ot * 64 + (tid & 63);

    __shared__ float cs[4][16];
    if (tid < 64) cs[tid >> 4][tid & 15] = cst[(it*4 + (tid >> 4))*NPIX + (tid & 15)];
    __syncthreads();

    const float coef = 1.0f / sqrtf(9.0f * (float)CH);
    float w9[9], q = 0.f;
    #pragma unroll
    for (int t = 0; t < 9; t++) {
        float w = conv_w[(size_t)t*CH*CH + (size_t)i*CH + o] * coef;
        w9[t] = w; q += w*w;
    }
    g_q[(size_t)i*CH + o] = q;

    float c16[NPIX];
    #pragma unroll
    for (int p = 0; p < NPIX; p++) c16[p] = cs[tid >> 6][p];

    u32 ph[8], pl[8];
    #pragma unroll
    for (int h = 0; h < 4; h++) {
        #pragma unroll
        for (int x2 = 0; x2 < 2; x2++) {
            float v[2];
            #pragma unroll
            for (int e = 0; e < 2; e++) {
                int x = x2*2 + e;
                float a = 0.f;
                #pragma unroll
                for (int kh = 0; kh < 3; kh++) {
                    int hh = h + kh - 1;
                    if (hh < 0 || hh >= 4) continue;
                    #pragma unroll
                    for (int kw = 0; kw < 3; kw++) {
                        int xx = x + kw - 1;
                        if (xx < 0 || xx >= 4) continue;
                        a += w9[kh*3 + kw] * c16[hh*4 + xx];
                    }
                }
                v[e] = a;
            }
            __nv_bfloat16 h0 = __float2bfloat16(v[0]);
            __nv_bfloat16 h1 = __float2bfloat16(v[1]);
            __nv_bfloat162 hp(h0, h1);
            __nv_bfloat162 lp(__float2bfloat16(v[0] - __bfloat162float(h0)),
                              __float2bfloat16(v[1] - __bfloat162float(h1)));
            ph[h*2 + x2] = *(u32*)&hp;
            pl[h*2 + x2] = *(u32*)&lp;
        }
    }
    uint4* dh = (uint4*)(g_Uh + (size_t)i*NCOL + o*16);
    uint4* dl = (uint4*)(g_Ul + (size_t)i*NCOL + o*16);
    dh[0] = make_uint4(ph[0], ph[1], ph[2], ph[3]);
    dh[1] = make_uint4(ph[4], ph[5], ph[6], ph[7]);
    dl[0] = make_uint4(pl[0], pl[1], pl[2], pl[3]);
    dl[1] = make_uint4(pl[4], pl[5], pl[6], pl[7]);
}

// ============== Kernel C: demod ==============
__global__ __launch_bounds__(512) void demod_kernel() {
    __shared__ float q_s[CH][9];
    const int tid = threadIdx.x;
    const int o0 = blockIdx.x * 8;
    {
        float4 a = *(const float4*)&g_q[(size_t)tid*CH + o0];
        float4 b = *(const float4*)&g_q[(size_t)tid*CH + o0 + 4];
        q_s[tid][0] = a.x; q_s[tid][1] = a.y; q_s[tid][2] = a.z; q_s[tid][3] = a.w;
        q_s[tid][4] = b.x; q_s[tid][5] = b.y; q_s[tid][6] = b.z; q_s[tid][7] = b.w;
    }
    __syncthreads();
    const int b = tid >> 3;
    const int og = tid & 7;
    float acc = 1e-8f;
    const float4* sp = (const float4*)&g_s2[(size_t)b*CH];
    #pragma unroll 4
    for (int i4 = 0; i4 < CH/4; i4++) {
        float4 s2v = sp[i4];
        acc = fmaf(s2v.x, q_s[i4*4+0][og], acc);
        acc = fmaf(s2v.y, q_s[i4*4+1][og], acc);
        acc = fmaf(s2v.z, q_s[i4*4+2][og], acc);
        acc = fmaf(s2v.w, q_s[i4*4+3][og], acc);
    }
    g_d[(size_t)b*CH + o0 + og] = rsqrtf(acc);
}

// ============== Kernel D: pipelined mma.sync GEMM + epilogue ==============
// grid 128; 256 threads = 8 warps (2 wm x 4 wn); 4-stage cp.async ring.
__global__ __launch_bounds__(256) void mma_kernel(
        const float* __restrict__ noise,
        const float* __restrict__ ns_ptr,
        const float* __restrict__ bias,
        float* __restrict__ out) {
    extern __shared__ __align__(16) char smem[];
    const u32 sm0 = smem_u32(smem);

    const int tid = threadIdx.x;
    const int wid = tid >> 5;
    const int lane = tid & 31;
    const int wm = wid >> 2;
    const int wn = wid & 3;
    const int n0 = blockIdx.x * TN;
    const int o0 = n0 >> 4;

    const int mrow = tid & 63;
    const int mat = tid >> 6;
    const __nv_bfloat16* src0;
    size_t step;
    if (mat == 0)      { src0 = g_Sh + (size_t)mrow*CH;        step = KCH; }
    else if (mat == 1) { src0 = g_Sl + (size_t)mrow*CH;        step = KCH; }
    else if (mat == 2) { src0 = g_Uh + (size_t)mrow*NCOL + n0; step = (size_t)KCH*NCOL; }
    else               { src0 = g_Ul + (size_t)mrow*NCOL + n0; step = (size_t)KCH*NCOL; }
    const u32 dst_off = (u32)(mat*MATB + mrow*ROWB);

    // prologue: stages 0..2
    #pragma unroll
    for (int p = 0; p < 3; p++) {
        u32 d = sm0 + p*STAGEB + dst_off;
        const __nv_bfloat16* s = src0 + (size_t)p*step;
        #pragma unroll
        for (int j = 0; j < 8; j++) cpasync16(d + j*16, s + j*8);
        CP_COMMIT();
    }

    const u32 aOff = (u32)(wm*32 + (lane & 15))*ROWB + (u32)(((lane >> 4) & 1)*16);
    const u32 bRow = (u32)(lane & 15)*ROWB;

    float acc[2][2][4];
    #pragma unroll
    for (int mf = 0; mf < 2; mf++)
        #pragma unroll
        for (int nf = 0; nf < 2; nf++)
            #pragma unroll
            for (int e = 0; e < 4; e++) acc[mf][nf][e] = 0.f;

    for (int ck = 0; ck < NCHUNK; ck++) {
        if (ck <= NCHUNK - 3) CP_WAIT(2);
        else if (ck == NCHUNK - 2) CP_WAIT(1);
        else CP_WAIT(0);
        __syncthreads();

        if (ck + 3 < NCHUNK) {
            int st = (ck + 3) % NSTAGE;
            u32 d = sm0 + st*STAGEB + dst_off;
            const __nv_bfloat16* s = src0 + (size_t)(ck + 3)*step;
            #pragma unroll
            for (int j = 0; j < 8; j++) cpasync16(d + j*16, s + j*8);
            CP_COMMIT();
        }

        const int st = ck % NSTAGE;
        const u32 ah_b = sm0 + st*STAGEB;
        const u32 al_b = ah_b + MATB;
        const u32 bh_b = ah_b + 2*MATB;
        const u32 bl_b = ah_b + 3*MATB;

        #pragma unroll
        for (int ks = 0; ks < 4; ks++) {
            u32 ah[2][4], al[2][4];
            ldsm_x4(ah[0], ah_b + aOff + (u32)(ks*32));
            ldsm_x4(ah[1], ah_b + aOff + 16*ROWB + (u32)(ks*32));
            ldsm_x4(al[0], al_b + aOff + (u32)(ks*32));
            ldsm_x4(al[1], al_b + aOff + 16*ROWB + (u32)(ks*32));
            const u32 krow = (u32)(ks*16)*ROWB + bRow;
            #pragma unroll
            for (int nf = 0; nf < 2; nf++) {
                u32 bh[2], bl[2];
                const u32 ncol = (u32)(wn*16 + nf*8)*2;
                ldsm_x2_trans(bh, bh_b + krow + ncol);
                ldsm_x2_trans(bl, bl_b + krow + ncol);
                #pragma unroll
                for (int mf = 0; mf < 2; mf++) {
                    mma16816(acc[mf][nf], ah[mf], bh);
                    mma16816(acc[mf][nf], ah[mf], bl);
                    mma16816(acc[mf][nf], al[mf], bh);
                }
            }
        }
    }
    __syncthreads();

    float* ep = (float*)smem;
    ep[tid] = g_d[(size_t)(tid & 63)*CH + o0 + (tid >> 6)];
    ((float4*)(ep + 256))[tid] = ((const float4*)noise)[tid];
    if (tid < 4) ep[1280 + tid] = bias[o0 + tid];
    if (tid == 4) ep[1284] = ns_ptr[0];
    __syncthreads();

    const float gain = 1.41421356237309515f;
    const float nstr = ep[1284];
    #pragma unroll
    for (int mf = 0; mf < 2; mf++) {
        #pragma unroll
        for (int nf = 0; nf < 2; nf++) {
            int row0 = wm*32 + mf*16 + (lane >> 2);
            int colb = wn*16 + nf*8 + 2*(lane & 3);
            int ol2 = colb >> 4;
            int px = colb & 15;
            float bb = ep[1280 + ol2];
            #pragma unroll
            for (int hh = 0; hh < 2; hh++) {
                int b = row0 + hh*8;
                float dv = ep[ol2*64 + b];
                float2 nz = *(const float2*)&ep[256 + b*NPIX + px];
                float x0 = acc[mf][nf][hh*2 + 0]*dv + nz.x*nstr + bb;
                float x1 = acc[mf][nf][hh*2 + 1]*dv + nz.y*nstr + bb;
                x0 = (x0 > 0.f ? x0 : 0.2f*x0)*gain;
                x1 = (x1 > 0.f ? x1 : 0.2f*x1)*gain;
                *(float2*)&out[(size_t)b*NCOL + n0 + colb] = make_float2(x0, x1);
            }
        }
    }
}

extern "C" void kernel_launch(void* const* d_in, const int* in_sizes, int n_in,
                              void* d_out, int out_size) {
    const float* w0     = (const float*)d_in[0];
    const float* cst    = (const float*)d_in[1];
    const float* conv_w = (const float*)d_in[2];
    const float* mod_w  = (const float*)d_in[3];
    const float* mod_b  = (const float*)d_in[4];
    const float* noise  = (const float*)d_in[5];
    const float* nstr   = (const float*)d_in[6];
    const float* bias   = (const float*)d_in[7];
    float* out = (float*)d_out;

    cudaFuncSetAttribute(mma_kernel,
        cudaFuncAttributeMaxDynamicSharedMemorySize, SMEM_MMA);

    uprep_kernel<<<1024, 256>>>(conv_w, cst);
    style_partial<<<64, 256>>>(w0, mod_w);
    style_finish<<<64, 512>>>(mod_b);
    demod_kernel<<<64, 512>>>();
    mma_kernel<<<NCOL / TN, 256, SMEM_MMA>>>(noise, nstr, bias, out);
}

// round 17
// speedup vs baseline: 1.6546x; 1.1587x over previous
#include <cuda_runtime.h>
#include <cuda_bf16.h>
#include <math.h>

typedef unsigned int u32;

#define BATCH 64
#define CH 512
#define WD 512
#define NPIX 16
#define NCOL (CH*NPIX)   /* 8192 */
#define TN 64
#define KCH 64
#define NCHUNK 8
#define ROWB 144
#define MATB (64*ROWB)   /* 9216 B */
#define STAGEB (4*MATB)  /* 36864 B */
#define NSTAGE 6
#define SMEM_MMA (NSTAGE*STAGEB)   /* 221184 B */

// ---- scratch ----
__device__ __align__(16) float g_sp[8][BATCH*CH];       // split-K partials (style, then demod)
__device__ __align__(16) float g_s2[BATCH*CH];
__device__ __align__(16) __nv_bfloat16 g_Sh[BATCH*CH];
__device__ __align__(16) __nv_bfloat16 g_Sl[BATCH*CH];
__device__ __align__(16) __nv_bfloat16 g_Uh[CH*NCOL];   // 8MB
__device__ __align__(16) __nv_bfloat16 g_Ul[CH*NCOL];   // 8MB
__device__ __align__(16) float g_q[CH*CH];
__device__ __align__(16) float g_d[BATCH*CH];

// ---- helpers ----
__device__ __forceinline__ u32 smem_u32(const void* p) {
    u32 a;
    asm("{ .reg .u64 t; cvta.to.shared.u64 t, %1; cvt.u32.u64 %0, t; }" : "=r"(a) : "l"(p));
    return a;
}
__device__ __forceinline__ void ldsm_x4(u32* r, u32 addr) {
    asm volatile("ldmatrix.sync.aligned.m8n8.x4.shared.b16 {%0,%1,%2,%3}, [%4];"
        : "=r"(r[0]), "=r"(r[1]), "=r"(r[2]), "=r"(r[3]) : "r"(addr));
}
__device__ __forceinline__ void ldsm_x2_trans(u32* r, u32 addr) {
    asm volatile("ldmatrix.sync.aligned.m8n8.x2.trans.shared.b16 {%0,%1}, [%2];"
        : "=r"(r[0]), "=r"(r[1]) : "r"(addr));
}
__device__ __forceinline__ void mma16816(float* c, const u32* a, const u32* b) {
    asm volatile("mma.sync.aligned.m16n8k16.row.col.f32.bf16.bf16.f32 "
        "{%0,%1,%2,%3}, {%4,%5,%6,%7}, {%8,%9}, {%0,%1,%2,%3};"
        : "+f"(c[0]), "+f"(c[1]), "+f"(c[2]), "+f"(c[3])
        : "r"(a[0]), "r"(a[1]), "r"(a[2]), "r"(a[3]), "r"(b[0]), "r"(b[1]));
}
__device__ __forceinline__ void cpasync16(u32 dst, const __nv_bfloat16* src) {
    asm volatile("cp.async.cg.shared.global [%0], [%1], 16;"
        :: "r"(dst), "l"(__cvta_generic_to_global((void*)src)));
}
#define CP_COMMIT() asm volatile("cp.async.commit_group;" ::: "memory")
#define CP_WAIT(n)  asm volatile("cp.async.wait_group %0;" :: "n"(n) : "memory")

// ============== Kernel A1: style split-K partial ==============
__global__ __launch_bounds__(256) void style_partial(
        const float* __restrict__ w0,
        const float* __restrict__ mod_w) {
    __shared__ float w0t[64][68];
    __shared__ float mwt[64][68];
    const int tid = threadIdx.x;
    const int ct = blockIdx.x >> 3;
    const int kt = blockIdx.x & 7;
    const int c0 = ct * 64;
    const int k0 = kt * 64;

    #pragma unroll
    for (int q = 0; q < 4; q++) {
        int idx = tid + q*256;
        int r = idx >> 4, c4 = idx & 15;
        *(float4*)&w0t[r][c4*4] = *(const float4*)&w0[r*WD + k0 + c4*4];
        *(float4*)&mwt[r][c4*4] = *(const float4*)&mod_w[(size_t)(k0 + r)*CH + c0 + c4*4];
    }
    __syncthreads();

    const int c  = tid & 63;
    const int bg = tid >> 6;
    float acc[16];
    #pragma unroll
    for (int i = 0; i < 16; i++) acc[i] = 0.f;

    #pragma unroll 8
    for (int k = 0; k < 64; k++) {
        float mw = mwt[k][c];
        #pragma unroll
        for (int i = 0; i < 16; i++)
            acc[i] = fmaf(w0t[bg*16 + i][k], mw, acc[i]);
    }
    #pragma unroll
    for (int i = 0; i < 16; i++)
        g_sp[kt][(size_t)(bg*16 + i)*CH + c0 + c] = acc[i];
}

// ============== Kernel A2: style finish ==============
__global__ __launch_bounds__(512) void style_finish(const float* __restrict__ mod_b) {
    const int b = blockIdx.x;
    const int c = threadIdx.x;
    const size_t idx = (size_t)b*CH + c;
    float a = 0.f;
    #pragma unroll
    for (int p = 0; p < 8; p++) a += g_sp[p][idx];
    const float inv = 1.0f / sqrtf((float)WD);
    float s = a*inv + mod_b[c] + 1.0f;
    g_s2[idx] = s*s;
    __nv_bfloat16 h = __float2bfloat16(s);
    g_Sh[idx] = h;
    g_Sl[idx] = __float2bfloat16(s - __bfloat162float(h));
}

// ============== Kernel B: U precompute (coalesced) ==============
__global__ __launch_bounds__(256) void uprep_kernel(
        const float* __restrict__ conv_w,
        const float* __restrict__ cst) {
    const int tid = threadIdx.x;
    const int it = blockIdx.x >> 3;
    const int ot = blockIdx.x & 7;
    const int i = it * 4 + (tid >> 6);
    const int o = ot * 64 + (tid & 63);

    __shared__ float cs[4][16];
    if (tid < 64) cs[tid >> 4][tid & 15] = cst[(it*4 + (tid >> 4))*NPIX + (tid & 15)];
    __syncthreads();

    const float coef = 1.0f / sqrtf(9.0f * (float)CH);
    float w9[9], q = 0.f;
    #pragma unroll
    for (int t = 0; t < 9; t++) {
        float w = conv_w[(size_t)t*CH*CH + (size_t)i*CH + o] * coef;
        w9[t] = w; q += w*w;
    }
    g_q[(size_t)i*CH + o] = q;

    float c16[NPIX];
    #pragma unroll
    for (int p = 0; p < NPIX; p++) c16[p] = cs[tid >> 6][p];

    u32 ph[8], pl[8];
    #pragma unroll
    for (int h = 0; h < 4; h++) {
        #pragma unroll
        for (int x2 = 0; x2 < 2; x2++) {
            float v[2];
            #pragma unroll
            for (int e = 0; e < 2; e++) {
                int x = x2*2 + e;
                float a = 0.f;
                #pragma unroll
                for (int kh = 0; kh < 3; kh++) {
                    int hh = h + kh - 1;
                    if (hh < 0 || hh >= 4) continue;
                    #pragma unroll
                    for (int kw = 0; kw < 3; kw++) {
                        int xx = x + kw - 1;
                        if (xx < 0 || xx >= 4) continue;
                        a += w9[kh*3 + kw] * c16[hh*4 + xx];
                    }
                }
                v[e] = a;
            }
            __nv_bfloat16 h0 = __float2bfloat16(v[0]);
            __nv_bfloat16 h1 = __float2bfloat16(v[1]);
            __nv_bfloat162 hp(h0, h1);
            __nv_bfloat162 lp(__float2bfloat16(v[0] - __bfloat162float(h0)),
                              __float2bfloat16(v[1] - __bfloat162float(h1)));
            ph[h*2 + x2] = *(u32*)&hp;
            pl[h*2 + x2] = *(u32*)&lp;
        }
    }
    uint4* dh = (uint4*)(g_Uh + (size_t)i*NCOL + o*16);
    uint4* dl = (uint4*)(g_Ul + (size_t)i*NCOL + o*16);
    dh[0] = make_uint4(ph[0], ph[1], ph[2], ph[3]);
    dh[1] = make_uint4(ph[4], ph[5], ph[6], ph[7]);
    dl[0] = make_uint4(pl[0], pl[1], pl[2], pl[3]);
    dl[1] = make_uint4(pl[4], pl[5], pl[6], pl[7]);
}

// ============== Kernel C1: demod split-K partial (tiled GEMM) ==============
// grid 64 = 8 o-tiles x 8 k-tiles; 256 threads. Reuses g_sp for partials.
__global__ __launch_bounds__(256) void demod_partial() {
    __shared__ float s2t[64][68];    // [b][k]
    __shared__ float qt [64][68];    // [k][o]
    const int tid = threadIdx.x;
    const int ot = blockIdx.x >> 3;
    const int kt = blockIdx.x & 7;
    const int o0 = ot * 64;
    const int k0 = kt * 64;

    #pragma unroll
    for (int q = 0; q < 4; q++) {
        int idx = tid + q*256;
        int r = idx >> 4, c4 = idx & 15;
        *(float4*)&s2t[r][c4*4] = *(const float4*)&g_s2[(size_t)r*CH + k0 + c4*4];
        *(float4*)&qt [r][c4*4] = *(const float4*)&g_q[(size_t)(k0 + r)*CH + o0 + c4*4];
    }
    __syncthreads();

    const int o  = tid & 63;
    const int bg = tid >> 6;
    float acc[16];
    #pragma unroll
    for (int i = 0; i < 16; i++) acc[i] = 0.f;

    #pragma unroll 8
    for (int k = 0; k < 64; k++) {
        float qv = qt[k][o];
        #pragma unroll
        for (int i = 0; i < 16; i++)
            acc[i] = fmaf(s2t[bg*16 + i][k], qv, acc[i]);
    }
    #pragma unroll
    for (int i = 0; i < 16; i++)
        g_sp[kt][(size_t)(bg*16 + i)*CH + o0 + o] = acc[i];
}

// ============== Kernel C2: demod finish ==============
__global__ __launch_bounds__(512) void demod_finish() {
    const int b = blockIdx.x;
    const int o = threadIdx.x;
    const size_t idx = (size_t)b*CH + o;
    float a = 1e-8f;
    #pragma unroll
    for (int p = 0; p < 8; p++) a += g_sp[p][idx];
    g_d[idx] = rsqrtf(a);
}

// ============== Kernel D: pipelined mma.sync GEMM + epilogue ==============
// grid 128; 256 threads = 8 warps (2 wm x 4 wn); 6-stage cp.async ring.
__global__ __launch_bounds__(256) void mma_kernel(
        const float* __restrict__ noise,
        const float* __restrict__ ns_ptr,
        const float* __restrict__ bias,
        float* __restrict__ out) {
    extern __shared__ __align__(16) char smem[];
    const u32 sm0 = smem_u32(smem);

    const int tid = threadIdx.x;
    const int wid = tid >> 5;
    const int lane = tid & 31;
    const int wm = wid >> 2;
    const int wn = wid & 3;
    const int n0 = blockIdx.x * TN;
    const int o0 = n0 >> 4;

    const int mrow = tid & 63;
    const int mat = tid >> 6;
    const __nv_bfloat16* src0;
    size_t step;
    if (mat == 0)      { src0 = g_Sh + (size_t)mrow*CH;        step = KCH; }
    else if (mat == 1) { src0 = g_Sl + (size_t)mrow*CH;        step = KCH; }
    else if (mat == 2) { src0 = g_Uh + (size_t)mrow*NCOL + n0; step = (size_t)KCH*NCOL; }
    else               { src0 = g_Ul + (size_t)mrow*NCOL + n0; step = (size_t)KCH*NCOL; }
    const u32 dst_off = (u32)(mat*MATB + mrow*ROWB);

    // prologue: stages 0..4
    #pragma unroll
    for (int p = 0; p < 5; p++) {
        u32 d = sm0 + p*STAGEB + dst_off;
        const __nv_bfloat16* s = src0 + (size_t)p*step;
        #pragma unroll
        for (int j = 0; j < 8; j++) cpasync16(d + j*16, s + j*8);
        CP_COMMIT();
    }

    const u32 aOff = (u32)(wm*32 + (lane & 15))*ROWB + (u32)(((lane >> 4) & 1)*16);
    const u32 bRow = (u32)(lane & 15)*ROWB;

    float acc[2][2][4];
    #pragma unroll
    for (int mf = 0; mf < 2; mf++)
        #pragma unroll
        for (int nf = 0; nf < 2; nf++)
            #pragma unroll
            for (int e = 0; e < 4; e++) acc[mf][nf][e] = 0.f;

    for (int ck = 0; ck < NCHUNK; ck++) {
        // stage ck must be complete: allow min(4, 7-ck) incomplete groups
        if (ck <= 3)      CP_WAIT(4);
        else if (ck == 4) CP_WAIT(3);
        else if (ck == 5) CP_WAIT(2);
        else if (ck == 6) CP_WAIT(1);
        else              CP_WAIT(0);
        __syncthreads();

        if (ck + 5 < NCHUNK) {
            int st = (ck + 5) % NSTAGE;
            u32 d = sm0 + st*STAGEB + dst_off;
            const __nv_bfloat16* s = src0 + (size_t)(ck + 5)*step;
            #pragma unroll
            for (int j = 0; j < 8; j++) cpasync16(d + j*16, s + j*8);
            CP_COMMIT();
        }

        const int st = ck % NSTAGE;
        const u32 ah_b = sm0 + st*STAGEB;
        const u32 al_b = ah_b + MATB;
        const u32 bh_b = ah_b + 2*MATB;
        const u32 bl_b = ah_b + 3*MATB;

        #pragma unroll
        for (int ks = 0; ks < 4; ks++) {
            u32 ah[2][4], al[2][4];
            ldsm_x4(ah[0], ah_b + aOff + (u32)(ks*32));
            ldsm_x4(ah[1], ah_b + aOff + 16*ROWB + (u32)(ks*32));
            ldsm_x4(al[0], al_b + aOff + (u32)(ks*32));
            ldsm_x4(al[1], al_b + aOff + 16*ROWB + (u32)(ks*32));
            const u32 krow = (u32)(ks*16)*ROWB + bRow;
            #pragma unroll
            for (int nf = 0; nf < 2; nf++) {
                u32 bh[2], bl[2];
                const u32 ncol = (u32)(wn*16 + nf*8)*2;
                ldsm_x2_trans(bh, bh_b + krow + ncol);
                ldsm_x2_trans(bl, bl_b + krow + ncol);
                #pragma unroll
                for (int mf = 0; mf < 2; mf++) {
                    mma16816(acc[mf][nf], ah[mf], bh);
                    mma16816(acc[mf][nf], ah[mf], bl);
                    mma16816(acc[mf][nf], al[mf], bh);
                }
            }
        }
    }
    __syncthreads();

    float* ep = (float*)smem;
    ep[tid] = g_d[(size_t)(tid & 63)*CH + o0 + (tid >> 6)];
    ((float4*)(ep + 256))[tid] = ((const float4*)noise)[tid];
    if (tid < 4) ep[1280 + tid] = bias[o0 + tid];
    if (tid == 4) ep[1284] = ns_ptr[0];
    __syncthreads();

    const float gain = 1.41421356237309515f;
    const float nstr = ep[1284];
    #pragma unroll
    for (int mf = 0; mf < 2; mf++) {
        #pragma unroll
        for (int nf = 0; nf < 2; nf++) {
            int row0 = wm*32 + mf*16 + (lane >> 2);
            int colb = wn*16 + nf*8 + 2*(lane & 3);
            int ol2 = colb >> 4;
            int px = colb & 15;
            float bb = ep[1280 + ol2];
            #pragma unroll
            for (int hh = 0; hh < 2; hh++) {
                int b = row0 + hh*8;
                float dv = ep[ol2*64 + b];
                float2 nz = *(const float2*)&ep[256 + b*NPIX + px];
                float x0 = acc[mf][nf][hh*2 + 0]*dv + nz.x*nstr + bb;
                float x1 = acc[mf][nf][hh*2 + 1]*dv + nz.y*nstr + bb;
                x0 = (x0 > 0.f ? x0 : 0.2f*x0)*gain;
                x1 = (x1 > 0.f ? x1 : 0.2f*x1)*gain;
                *(float2*)&out[(size_t)b*NCOL + n0 + colb] = make_float2(x0, x1);
            }
        }
    }
}

extern "C" void kernel_launch(void* const* d_in, const int* in_sizes, int n_in,
                              void* d_out, int out_size) {
    const float* w0     = (const float*)d_in[0];
    const float* cst    = (const float*)d_in[1];
    const float* conv_w = (const float*)d_in[2];
    const float* mod_w  = (const float*)d_in[3];
    const float* mod_b  = (const float*)d_in[4];
    const float* noise  = (const float*)d_in[5];
    const float* nstr   = (const float*)d_in[6];
    const float* bias   = (const float*)d_in[7];
    float* out = (float*)d_out;

    cudaFuncSetAttribute(mma_kernel,
        cudaFuncAttributeMaxDynamicSharedMemorySize, SMEM_MMA);

    uprep_kernel<<<1024, 256>>>(conv_w, cst);
    style_partial<<<64, 256>>>(w0, mod_w);
    style_finish<<<64, 512>>>(mod_b);
    demod_partial<<<64, 256>>>();
    demod_finish<<<64, 512>>>();
    mma_kernel<<<NCOL / TN, 256, SMEM_MMA>>>(noise, nstr, bias, out);
}